// round 17
// baseline (speedup 1.0000x reference)
#include <cuda_runtime.h>
#include <cuda_fp16.h>
#include <cuda_bf16.h>
#include <stdint.h>
#include <math.h>

// Problem constants
#define BATCH 4
#define SEQ   2048
#define DIM   1024
#define HEADS 16
#define HDIM  64
#define MROWS (BATCH * SEQ)          // 8192
#define QKVN  (3 * DIM)              // 3072
#define K3    3072
#define PLANE ((size_t)BATCH * HEADS * SEQ * HDIM)   // 8388608 halves / plane

// Scratch (device globals; no dynamic allocation allowed)
__device__ __nv_bfloat16 g_abuf[(size_t)MROWS * K3];   // x fp16, later ctx fp16
__device__ __nv_bfloat16 g_bbuf[(size_t)QKVN * K3];    // in_proj_w fp16
__device__ __half g_wo16[(size_t)DIM * DIM];           // out_w fp16
__device__ __half g_f16[3 * PLANE];                    // Qh,Kh,Vh planes
__device__ float g_att[(size_t)MROWS * DIM];           // out-proj result

// ===========================================================================
// Helpers (base-ISA only: cp.async, ldmatrix, mma.sync)
// ===========================================================================
__device__ __forceinline__ uint32_t smem_u32(const void* p) {
    uint32_t a;
    asm("{ .reg .u64 t; cvta.to.shared.u64 t, %1; cvt.u32.u64 %0, t; }"
        : "=r"(a) : "l"(p));
    return a;
}
__device__ __forceinline__ void cp_async16(uint32_t dst, const void* src) {
    asm volatile("cp.async.cg.shared.global [%0], [%1], 16;"
                 :: "r"(dst), "l"(src) : "memory");
}
#define CP_COMMIT() asm volatile("cp.async.commit_group;" ::: "memory")
#define CP_WAIT(n)  asm volatile("cp.async.wait_group %0;" :: "n"(n) : "memory")

__device__ __forceinline__ void ldmatrix_x4(uint32_t& r0, uint32_t& r1,
                                            uint32_t& r2, uint32_t& r3,
                                            uint32_t addr) {
    asm volatile("ldmatrix.sync.aligned.m8n8.x4.shared.b16 {%0,%1,%2,%3}, [%4];"
                 : "=r"(r0), "=r"(r1), "=r"(r2), "=r"(r3) : "r"(addr));
}
__device__ __forceinline__ void ldmatrix_x4_trans(uint32_t& r0, uint32_t& r1,
                                                  uint32_t& r2, uint32_t& r3,
                                                  uint32_t addr) {
    asm volatile("ldmatrix.sync.aligned.m8n8.x4.trans.shared.b16 {%0,%1,%2,%3}, [%4];"
                 : "=r"(r0), "=r"(r1), "=r"(r2), "=r"(r3) : "r"(addr));
}
__device__ __forceinline__ void mma_f16(float* d, const uint32_t* a,
                                        uint32_t b0, uint32_t b1) {
    asm volatile(
        "mma.sync.aligned.m16n8k16.row.col.f32.f16.f16.f32 "
        "{%0,%1,%2,%3}, {%4,%5,%6,%7}, {%8,%9}, {%0,%1,%2,%3};"
        : "+f"(d[0]), "+f"(d[1]), "+f"(d[2]), "+f"(d[3])
        : "r"(a[0]), "r"(a[1]), "r"(a[2]), "r"(a[3]), "r"(b0), "r"(b1));
}
__device__ __forceinline__ uint32_t packh2(float a, float b) {
    __half2 h = __floats2half2_rn(a, b);
    return *(uint32_t*)&h;
}

// ===========================================================================
// Fused fp32 -> fp16 conversion of x | w_in | w_out (one float4 per thread)
// ===========================================================================
#define XF4   ((MROWS * DIM) / 4)          // 2097152
#define WIF4  ((QKVN * DIM) / 4)           // 786432
#define WOF4  ((DIM * DIM) / 4)            // 262144
#define CONVF4 (XF4 + WIF4 + WOF4)         // 3145728

__global__ __launch_bounds__(256) void conv_all_kernel(
    const float* __restrict__ x, const float* __restrict__ w_in,
    const float* __restrict__ w_out,
    __half* __restrict__ xo, __half* __restrict__ wio,
    __half* __restrict__ woo)
{
    const int i = blockIdx.x * 256 + threadIdx.x;
    const float* src;
    __half* dst;
    int j;
    if (i < XF4)              { src = x;     dst = xo;  j = i; }
    else if (i < XF4 + WIF4)  { src = w_in;  dst = wio; j = i - XF4; }
    else                      { src = w_out; dst = woo; j = i - XF4 - WIF4; }
    float4 v = ((const float4*)src)[j];
    uint2 H;
    H.x = packh2(v.x, v.y);
    H.y = packh2(v.z, v.w);
    *(uint2*)(dst + (size_t)j * 4) = H;
}

// ===========================================================================
// mma.sync fp16 GEMM: 128x256 CTA tile, K=1024, BK=64, 3-stage cp.async.
// 8 warps (2m x 4n), warp tile 64x64 (acc = 128 regs). 1 CTA/SM, full RF.
// MODE=0: fp32 out + bias.  MODE=1: QKV -> fp16 planes Q(0,scaled 1/8),K(1),V(2)
// ===========================================================================
#define BK 64
#define GKLEN 1024
#define STG 3
#define ROWB 144                         // 128 B data + 16 B pad
#define TILEA (128 * ROWB)               // 18432 B (A stage)
#define TILEB2 (256 * ROWB)              // 36864 B (B stage)
#define GEMM_SMEM (STG * (TILEA + TILEB2))   // 165888 B

__device__ __forceinline__ void g_load_tiles(
    const __half* __restrict__ Ab, const __half* __restrict__ Bb,
    uint32_t sA, uint32_t sB, int stage, int chunk, int tid)
{
    const uint32_t sa = sA + stage * TILEA;
    const uint32_t sb = sB + stage * TILEB2;
    // A: 128 rows x 8 chunks = 1024 cp
#pragma unroll
    for (int i = 0; i < 4; i++) {
        int idx = tid + i * 256;
        int row = idx >> 3;
        int cc = idx & 7;
        cp_async16(sa + row * ROWB + cc * 16,
                   Ab + (size_t)row * GKLEN + chunk * BK + cc * 8);
    }
    // B: 256 rows x 8 chunks = 2048 cp
#pragma unroll
    for (int i = 0; i < 8; i++) {
        int idx = tid + i * 256;
        int row = idx >> 3;
        int cc = idx & 7;
        cp_async16(sb + row * ROWB + cc * 16,
                   Bb + (size_t)row * GKLEN + chunk * BK + cc * 8);
    }
}

template <int MODE>
__global__ __launch_bounds__(256, 1) void gemm_mma(
    const __half* __restrict__ A, const __half* __restrict__ B,
    const float* __restrict__ bias, float* __restrict__ C,
    __half* __restrict__ f16out, int N)
{
    extern __shared__ __align__(16) char smem[];
    const uint32_t sA = smem_u32(smem);
    const uint32_t sB = sA + STG * TILEA;

    const int tid = threadIdx.x;
    const int warp = tid >> 5;
    const int lane = tid & 31;
    const int wm = warp >> 2;            // 0..1 -> m offset wm*64
    const int wn = warp & 3;             // 0..3 -> n offset wn*64
    const int bm = blockIdx.y * 128;
    const int bn = blockIdx.x * 256;
    const int NC = GKLEN / BK;           // 16

    const __half* Ab = A + (size_t)bm * GKLEN;
    const __half* Bb = B + (size_t)bn * GKLEN;

    float acc[4][8][4];
#pragma unroll
    for (int mt = 0; mt < 4; mt++)
#pragma unroll
        for (int nt = 0; nt < 8; nt++)
#pragma unroll
            for (int r = 0; r < 4; r++) acc[mt][nt][r] = 0.0f;

    const int lrow = lane & 15;
    const int lcol = (lane >> 4) * 16;

#pragma unroll
    for (int c = 0; c < STG - 1; c++) {
        g_load_tiles(Ab, Bb, sA, sB, c, c, tid);
        CP_COMMIT();
    }

    for (int c = 0; c < NC; c++) {
        CP_WAIT(STG - 2);
        __syncthreads();                 // data c visible; stage (c+2)%3 free

        const int t = c + STG - 1;
        if (t < NC) g_load_tiles(Ab, Bb, sA, sB, t % STG, t, tid);
        CP_COMMIT();

        const int s = c % STG;
        const uint32_t aBase = sA + s * TILEA;
        const uint32_t bBase = sB + s * TILEB2;

#pragma unroll
        for (int ks = 0; ks < 4; ks++) {
            const int kb = ks * 32;      // byte offset of 16-elem k-slice
            uint32_t af[4][4];
#pragma unroll
            for (int mt = 0; mt < 4; mt++) {
                uint32_t addr = aBase + (wm * 64 + mt * 16 + lrow) * ROWB
                              + kb + lcol;
                ldmatrix_x4(af[mt][0], af[mt][1], af[mt][2], af[mt][3], addr);
            }
            uint32_t bf[4][4];
#pragma unroll
            for (int bt = 0; bt < 4; bt++) {
                uint32_t addr = bBase + (wn * 64 + bt * 16 + lrow) * ROWB
                              + kb + lcol;
                ldmatrix_x4(bf[bt][0], bf[bt][1], bf[bt][2], bf[bt][3], addr);
            }
#pragma unroll
            for (int mt = 0; mt < 4; mt++)
#pragma unroll
                for (int nt = 0; nt < 8; nt++) {
                    const int bt = nt >> 1, sel = nt & 1;
                    mma_f16(acc[mt][nt], af[mt], bf[bt][sel], bf[bt][sel + 2]);
                }
        }
    }

    const int er = lane >> 2;
    const int ec = (lane & 3) * 2;
#pragma unroll
    for (int mt = 0; mt < 4; mt++) {
#pragma unroll
        for (int nt = 0; nt < 8; nt++) {
            const int col = bn + wn * 64 + nt * 8 + ec;
            const float b0 = bias[col], b1 = bias[col + 1];
            const int r0 = bm + wm * 64 + mt * 16 + er;
            float v00 = acc[mt][nt][0] + b0, v01 = acc[mt][nt][1] + b1;
            float v10 = acc[mt][nt][2] + b0, v11 = acc[mt][nt][3] + b1;
            if (MODE == 0) {
                *(float2*)(C + (size_t)r0 * N + col) = {v00, v01};
                *(float2*)(C + (size_t)(r0 + 8) * N + col) = {v10, v11};
            } else {
                const int type = col >> 10;           // 0=Q 1=K 2=V
                const int rem = col & 1023;
                const int h = rem >> 6;
                const int d = rem & 63;
                if (type == 0) { v00 *= 0.125f; v01 *= 0.125f;
                                 v10 *= 0.125f; v11 *= 0.125f; }
                const int b = r0 >> 11;
                const int s0 = r0 & 2047;
                size_t rowbase = (((size_t)(b * HEADS + h)) * SEQ + s0) * HDIM + d;
                __half* hp = f16out + (size_t)type * PLANE;
#pragma unroll
                for (int rr = 0; rr < 2; rr++) {
                    float vx = rr ? v10 : v00;
                    float vy = rr ? v11 : v01;
                    __half2 t = {__float2half_rn(vx), __float2half_rn(vy)};
                    *(__half2*)(hp + rowbase + (size_t)rr * 8 * HDIM) = t;
                }
            }
        }
    }
}

// ===========================================================================
// Flash attention (tensor cores), 2 CTAs/SM, pure fp16, 3-stage K/V ring,
// ONE __syncthreads per key tile. (unchanged from R16)
// smem = Qh (18432) + 3 stages x (Kh|Vh @ 64x144B) = 73728 B.
// ===========================================================================
#define FROWB 144
#define FTILE 9216                       // 64 * 144
#define FSTAGE (2 * FTILE)               // 18432 (Kh|Vh)
#define FQREG  (128 * FROWB)             // 18432 (Qh)
#define FLASH_SMEM (FQREG + 3 * FSTAGE)  // 73728

__global__ __launch_bounds__(256, 2) void flash_mma(
    const __half* __restrict__ f16, __half* __restrict__ ctx16)
{
    extern __shared__ __align__(16) char fsm[];
    const uint32_t sb = smem_u32(fsm);

    const int tid = threadIdx.x;
    const int w = tid >> 5;
    const int lane = tid & 31;
    const int er = lane >> 2;
    const int ec = (lane & 3) * 2;
    const int lrow = lane & 15;
    const int lcol = (lane >> 4) * 16;

    const int qt = (int)gridDim.x - 1 - (int)blockIdx.x;   // heavy tiles first
    const int h = blockIdx.y;
    const int b = blockIdx.z;
    const int q0 = qt * 128;

    const size_t hb = ((size_t)(b * HEADS + h)) * SEQ * HDIM;
    const __half* Qhg = f16 + hb;
    const __half* Khg = f16 + PLANE + hb;
    const __half* Vhg = f16 + 2 * PLANE + hb;

    // ---- stage Q into the persistent region ----
#pragma unroll
    for (int i = 0; i < 4; i++) {
        int idx = tid + i * 256;
        int r = idx >> 3;
        int c = idx & 7;
        cp_async16(sb + r * FROWB + c * 16,
                   Qhg + (size_t)(q0 + r) * HDIM + c * 8);
    }
    CP_COMMIT();

    float o[8][4];
#pragma unroll
    for (int nf = 0; nf < 8; nf++)
#pragma unroll
        for (int r = 0; r < 4; r++) o[nf][r] = 0.0f;
    float mprev[2] = {-INFINITY, -INFINITY};
    float lsum[2] = {0.0f, 0.0f};

    const int nkt = 2 * qt + 2;

    auto issue_tile = [&](int kt, int st) {
        const int k0 = kt * 64;
        const uint32_t sbase = sb + FQREG + st * FSTAGE;
#pragma unroll
        for (int i = 0; i < 4; i++) {
            int idx = tid + i * 256;
            int op = idx >> 9;
            int within = idx & 511;
            int r = within >> 3;
            int c = within & 7;
            const __half* base = (op == 0) ? Khg : Vhg;
            cp_async16(sbase + op * FTILE + r * FROWB + c * 16,
                       base + (size_t)(k0 + r) * HDIM + c * 8);
        }
        CP_COMMIT();
    };

    issue_tile(0, 0);
    if (nkt > 1) issue_tile(1, 1);

    for (int kt = 0; kt < nkt; kt++) {
        const int k0 = kt * 64;
        if (kt + 1 < nkt) { CP_WAIT(1); }
        else              { CP_WAIT(0); }
        __syncthreads();

        const int t = kt + 2;
        if (t < nkt) issue_tile(t, t % 3);

        const uint32_t Kh = sb + FQREG + (kt % 3) * FSTAGE;
        const uint32_t Vh = Kh + FTILE;

        // ---- S = Q K^T ----
        float s[8][4];
#pragma unroll
        for (int nf = 0; nf < 8; nf++)
#pragma unroll
            for (int r = 0; r < 4; r++) s[nf][r] = 0.0f;

#pragma unroll
        for (int ks = 0; ks < 4; ks++) {
            uint32_t qh4[4];
            uint32_t qa = sb + (w * 16 + lrow) * FROWB + ks * 32 + lcol;
            ldmatrix_x4(qh4[0], qh4[1], qh4[2], qh4[3], qa);
#pragma unroll
            for (int g = 0; g < 4; g++) {
                uint32_t kh4[4];
                uint32_t a = Kh + (g * 16 + lrow) * FROWB + ks * 32 + lcol;
                ldmatrix_x4(kh4[0], kh4[1], kh4[2], kh4[3], a);
                mma_f16(s[2 * g],     qh4, kh4[0], kh4[2]);
                mma_f16(s[2 * g + 1], qh4, kh4[1], kh4[3]);
            }
        }

        // ---- causal mask ----
        if (kt >= 2 * qt) {
            const int row0 = q0 + w * 16 + er;
#pragma unroll
            for (int nf = 0; nf < 8; nf++) {
                const int keyb = k0 + (nf >> 1) * 16 + (nf & 1) * 8 + ec;
#pragma unroll
                for (int r = 0; r < 4; r++) {
                    int key = keyb + (r & 1);
                    int row = row0 + (r >> 1) * 8;
                    if (key > row) s[nf][r] = -INFINITY;
                }
            }
        }

        // ---- online softmax ----
        float mx0 = -INFINITY, mx1 = -INFINITY;
#pragma unroll
        for (int nf = 0; nf < 8; nf++) {
            mx0 = fmaxf(mx0, fmaxf(s[nf][0], s[nf][1]));
            mx1 = fmaxf(mx1, fmaxf(s[nf][2], s[nf][3]));
        }
        mx0 = fmaxf(mx0, __shfl_xor_sync(0xffffffffu, mx0, 1));
        mx0 = fmaxf(mx0, __shfl_xor_sync(0xffffffffu, mx0, 2));
        mx1 = fmaxf(mx1, __shfl_xor_sync(0xffffffffu, mx1, 1));
        mx1 = fmaxf(mx1, __shfl_xor_sync(0xffffffffu, mx1, 2));

        float mn0 = fmaxf(mprev[0], mx0);
        float mn1 = fmaxf(mprev[1], mx1);
        float al0 = __expf(mprev[0] - mn0);
        float al1 = __expf(mprev[1] - mn1);
        float sum0 = 0.0f, sum1 = 0.0f;
#pragma unroll
        for (int nf = 0; nf < 8; nf++) {
            s[nf][0] = __expf(s[nf][0] - mn0);
            s[nf][1] = __expf(s[nf][1] - mn0);
            s[nf][2] = __expf(s[nf][2] - mn1);
            s[nf][3] = __expf(s[nf][3] - mn1);
            sum0 += s[nf][0] + s[nf][1];
            sum1 += s[nf][2] + s[nf][3];
        }
        sum0 += __shfl_xor_sync(0xffffffffu, sum0, 1);
        sum0 += __shfl_xor_sync(0xffffffffu, sum0, 2);
        sum1 += __shfl_xor_sync(0xffffffffu, sum1, 1);
        sum1 += __shfl_xor_sync(0xffffffffu, sum1, 2);
        lsum[0] = lsum[0] * al0 + sum0;
        lsum[1] = lsum[1] * al1 + sum1;
        mprev[0] = mn0;
        mprev[1] = mn1;
#pragma unroll
        for (int nf = 0; nf < 8; nf++) {
            o[nf][0] *= al0; o[nf][1] *= al0;
            o[nf][2] *= al1; o[nf][3] *= al1;
        }

        // ---- O += P Vh ----
#pragma unroll
        for (int kk = 0; kk < 4; kk++) {
            uint32_t pa[4];
            pa[0] = packh2(s[2 * kk][0], s[2 * kk][1]);
            pa[1] = packh2(s[2 * kk][2], s[2 * kk][3]);
            pa[2] = packh2(s[2 * kk + 1][0], s[2 * kk + 1][1]);
            pa[3] = packh2(s[2 * kk + 1][2], s[2 * kk + 1][3]);
#pragma unroll
            for (int g = 0; g < 4; g++) {
                uint32_t vh4[4];
                uint32_t a = Vh + (kk * 16 + lrow) * FROWB + g * 32 + lcol;
                ldmatrix_x4_trans(vh4[0], vh4[1], vh4[2], vh4[3], a);
                mma_f16(o[2 * g],     pa, vh4[0], vh4[1]);
                mma_f16(o[2 * g + 1], pa, vh4[2], vh4[3]);
            }
        }
    }

    // ---- normalize + write ctx fp16 rows [MROWS][1024] ----
    const float inv0 = 1.0f / lsum[0];
    const float inv1 = 1.0f / lsum[1];
    const int mrow0 = b * SEQ + q0 + w * 16 + er;
#pragma unroll
    for (int nf = 0; nf < 8; nf++) {
        const int c = h * HDIM + nf * 8 + ec;
#pragma unroll
        for (int rr = 0; rr < 2; rr++) {
            float vx = o[nf][2 * rr + 0] * (rr ? inv1 : inv0);
            float vy = o[nf][2 * rr + 1] * (rr ? inv1 : inv0);
            __half2 t = {__float2half_rn(vx), __float2half_rn(vy)};
            *(__half2*)(ctx16 + (size_t)(mrow0 + rr * 8) * DIM + c) = t;
        }
    }
}

// ===========================================================================
// Residual + LayerNorm (unchanged)
// ===========================================================================
__global__ __launch_bounds__(256) void ln_kernel(
    const float* __restrict__ x, const float* __restrict__ att,
    const float* __restrict__ gamma, const float* __restrict__ beta,
    float* __restrict__ out)
{
    __shared__ float red[2][8];
    const int row = blockIdx.x;
    const int tid = threadIdx.x;
    const float* xr = x + (size_t)row * DIM;
    const float* ar = att + (size_t)row * DIM;

    float v[4];
    float s = 0.0f, s2 = 0.0f;
#pragma unroll
    for (int i = 0; i < 4; i++) {
        int c = tid + i * 256;
        float t = xr[c] + ar[c];
        v[i] = t;
        s += t;
        s2 += t * t;
    }
#pragma unroll
    for (int off = 16; off >= 1; off >>= 1) {
        s  += __shfl_xor_sync(0xffffffffu, s, off);
        s2 += __shfl_xor_sync(0xffffffffu, s2, off);
    }
    if ((tid & 31) == 0) { red[0][tid >> 5] = s; red[1][tid >> 5] = s2; }
    __syncthreads();
    s = 0.0f; s2 = 0.0f;
#pragma unroll
    for (int k = 0; k < 8; k++) { s += red[0][k]; s2 += red[1][k]; }

    const float mu = s * (1.0f / DIM);
    const float var = s2 * (1.0f / DIM) - mu * mu;
    const float rs = rsqrtf(var + 1e-5f);

    float* orow = out + (size_t)row * DIM;
#pragma unroll
    for (int i = 0; i < 4; i++) {
        int c = tid + i * 256;
        orow[c] = (v[i] - mu) * rs * gamma[c] + beta[c];
    }
}

// ===========================================================================
// Launch
// ===========================================================================
extern "C" void kernel_launch(void* const* d_in, const int* in_sizes, int n_in,
                              void* d_out, int out_size)
{
    const float* x      = (const float*)d_in[0];
    const float* w_in   = (const float*)d_in[1];
    const float* b_in   = (const float*)d_in[2];
    const float* w_out  = (const float*)d_in[3];
    const float* b_out  = (const float*)d_in[4];
    const float* gamma  = (const float*)d_in[5];
    const float* beta   = (const float*)d_in[6];
    float* out = (float*)d_out;

    void* p;
    cudaGetSymbolAddress(&p, g_abuf);  __half* abuf = (__half*)p;
    cudaGetSymbolAddress(&p, g_bbuf);  __half* wi16 = (__half*)p;
    cudaGetSymbolAddress(&p, g_wo16);  __half* wo16 = (__half*)p;
    cudaGetSymbolAddress(&p, g_f16);   __half* f16 = (__half*)p;
    cudaGetSymbolAddress(&p, g_att);   float* att = (float*)p;

    cudaFuncSetAttribute(gemm_mma<0>,
                         cudaFuncAttributeMaxDynamicSharedMemorySize, GEMM_SMEM);
    cudaFuncSetAttribute(gemm_mma<1>,
                         cudaFuncAttributeMaxDynamicSharedMemorySize, GEMM_SMEM);
    cudaFuncSetAttribute(flash_mma,
                         cudaFuncAttributeMaxDynamicSharedMemorySize, FLASH_SMEM);

    // 1) fused fp32->fp16 conversion of x, in_proj_w, out_w
    conv_all_kernel<<<CONVF4 / 256, 256>>>(x, w_in, w_out, abuf, wi16, wo16);

    // 2) QKV projection (single fp16 GEMM, K=1024) -> Q,K,V planes
    gemm_mma<1><<<dim3(QKVN / 256, MROWS / 128), 256, GEMM_SMEM>>>(
        abuf, wi16, b_in, nullptr, f16, QKVN);

    // 3) causal flash attention -> ctx fp16 [MROWS][1024] (reuses abuf)
    flash_mma<<<dim3(SEQ / 128, HEADS, BATCH), 256, FLASH_SMEM>>>(f16, abuf);

    // 4) out projection (fp16, K=1024)
    gemm_mma<0><<<dim3(DIM / 256, MROWS / 128), 256, GEMM_SMEM>>>(
        abuf, wo16, b_out, att, nullptr, DIM);

    // 5) residual + layernorm
    ln_kernel<<<MROWS, 256>>>(x, att, gamma, beta, out);
}